// round 16
// baseline (speedup 1.0000x reference)
#include <cuda_runtime.h>
#include <cuda_fp16.h>
#include <math.h>

#define D        64
#define NU       50000
#define NB       20000
#define NI       100000
#define N_UB     (NU + NB)
#define N_UI     (NU + NI)
#define N_BI     (NB + NI)
#define N_TOT    (N_UB + N_UI + N_BI)       /* 340000 */
#define OFF_UB   0
#define OFF_UI   N_UB                        /* 70000 */
#define OFF_BI   (N_UB + N_UI)               /* 220000 */
#define NFEAT    (NU + NB + NI)              /* 170000 */
#define HOFF_U   0
#define HOFF_B   NU
#define HOFF_I   (NU + NB)
#define MAXDEG   50
#define BATCH    2048
#define NCAND    2
#define CORE_K   3
#define EMAXTOT  3000000
#define SCAN_TILE 2048

// ---------------- scratch (allocation-free rule: device globals) ----------------
__device__ __half g_hf[(size_t)NFEAT * D];     // fp16 base features (U, B, I)
__device__ __half g_y1[(size_t)N_TOT * D];     // fp16 layer-1 output
__device__ __half g_repUB[(size_t)N_UB * D];   // final reps (fp16)
__device__ __half g_repUI[(size_t)N_UI * D];
__device__ __half g_repBI[(size_t)N_BI * D];
__device__ int    g_cnt[N_TOT];                // counts -> cursor
__device__ int    g_rowptr[N_TOT + 1];
__device__ int    g_part[256];
__device__ int2   g_ccv[EMAXTOT];              // packed (col, val bits)
__device__ float  g_scores[BATCH * NCAND];

// ---------------- f2h + zero cnt ----------------
__global__ void f2h_kernel(const float4* __restrict__ uf, const float4* __restrict__ bf,
                           const float4* __restrict__ itf, uint2* __restrict__ dst,
                           int* __restrict__ cnt) {
    int i = blockIdx.x * blockDim.x + threadIdx.x;
    if (i < N_TOT) cnt[i] = 0;
    const int nU = NU * 16, nB = NB * 16, nI = NI * 16;
    float4 v;
    if (i < nU) v = __ldg(uf + i);
    else if (i < nU + nB) v = __ldg(bf + (i - nU));
    else if (i < nU + nB + nI) v = __ldg(itf + (i - nU - nB));
    else return;
    __half2 h0 = __floats2half2_rn(v.x, v.y);
    __half2 h1 = __floats2half2_rn(v.z, v.w);
    uint2 o;
    o.x = *reinterpret_cast<unsigned*>(&h0);
    o.y = *reinterpret_cast<unsigned*>(&h1);
    dst[i] = o;
}

// ---------------- CSR build (batched over all 3 graphs) ----------------

__global__ void hist_all_kernel(const int* __restrict__ ubr, const int* __restrict__ uir,
                                const int* __restrict__ bir,
                                int Eub, int Eui, int Ebi,
                                int* __restrict__ cnt) {
    int e = blockIdx.x * blockDim.x + threadIdx.x;
    int r;
    if (e < Eub) r = __ldg(ubr + e) + OFF_UB;
    else if (e < Eub + Eui) r = __ldg(uir + (e - Eub)) + OFF_UI;
    else if (e < Eub + Eui + Ebi) r = __ldg(bir + (e - Eub - Eui)) + OFF_BI;
    else return;
    atomicAdd(&cnt[r], 1);
}

__global__ void scan1_kernel(int* __restrict__ data, int* __restrict__ part, int n) {
    __shared__ int sh[256];
    int tid = threadIdx.x;
    int base = blockIdx.x * SCAN_TILE + tid * 8;
    int v[8];
    int s = 0;
    #pragma unroll
    for (int k = 0; k < 8; k++) {
        v[k] = (base + k < n) ? data[base + k] : 0;
        s += v[k];
    }
    sh[tid] = s;
    __syncthreads();
    #pragma unroll
    for (int off = 1; off < 256; off <<= 1) {
        int t = (tid >= off) ? sh[tid - off] : 0;
        __syncthreads();
        sh[tid] += t;
        __syncthreads();
    }
    if (tid == 255) part[blockIdx.x] = sh[255];
    int run = sh[tid] - s;
    #pragma unroll
    for (int k = 0; k < 8; k++) {
        if (base + k < n) data[base + k] = run;
        run += v[k];
    }
}

__global__ void scan3_kernel(int* __restrict__ data, const int* __restrict__ part,
                             int* __restrict__ rowptr, int n, int np, int E) {
    __shared__ int sh[256];
    int tid = threadIdx.x;
    int s = (tid < np) ? part[tid] : 0;
    sh[tid] = s;
    __syncthreads();
    #pragma unroll
    for (int off = 1; off < 256; off <<= 1) {
        int t = (tid >= off) ? sh[tid - off] : 0;
        __syncthreads();
        sh[tid] += t;
        __syncthreads();
    }
    __syncthreads();
    int i = blockIdx.x * blockDim.x + tid;
    if (i < n) {
        int blk = i / SCAN_TILE;
        int v = data[i] + sh[blk] - ((blk < np) ? part[blk] : 0);
        rowptr[i] = v;
        data[i] = v;
    }
    if (i == 0) rowptr[n] = E;
}

__global__ void scatter_all_kernel(const int* __restrict__ ubr, const int* __restrict__ ubc,
                                   const float* __restrict__ ubv,
                                   const int* __restrict__ uir, const int* __restrict__ uic,
                                   const float* __restrict__ uiv,
                                   const int* __restrict__ bir, const int* __restrict__ bic,
                                   const float* __restrict__ biv,
                                   int Eub, int Eui, int Ebi,
                                   int* __restrict__ cursor,
                                   int2* __restrict__ ccv) {
    int e = blockIdx.x * blockDim.x + threadIdx.x;
    int r, c; float v;
    if (e < Eub) { r = __ldg(ubr + e) + OFF_UB; c = __ldg(ubc + e); v = __ldg(ubv + e); }
    else if (e < Eub + Eui) { int t = e - Eub; r = __ldg(uir + t) + OFF_UI; c = __ldg(uic + t); v = __ldg(uiv + t); }
    else if (e < Eub + Eui + Ebi) { int t = e - Eub - Eui; r = __ldg(bir + t) + OFF_BI; c = __ldg(bic + t); v = __ldg(biv + t); }
    else return;
    int p = atomicAdd(&cursor[r], 1);
    ccv[p] = make_int2(c, __float_as_int(v));
}

// ---------------- fused gather spmm, fp16 rows, 16 lanes/row, 2-deep ----------------
template <bool FIN>
__global__ void __launch_bounds__(256)
spmm_all_kernel(const int* __restrict__ rowptr, const int2* __restrict__ ccv,
                const __half* __restrict__ hf, __half* __restrict__ y1,
                __half* __restrict__ repUB, __half* __restrict__ repUI,
                __half* __restrict__ repBI) {
    int g = blockIdx.x * blockDim.x + threadIdx.x;
    int r = g >> 4;
    if (r >= N_TOT) return;
    int lane = threadIdx.x & 31;
    int sub = lane & 15;
    unsigned mask = (lane < 16) ? 0x0000FFFFu : 0xFFFF0000u;

    const uint2* ha; const uint2* hb; int na; int off; __half* rep;
    const uint2* hU = reinterpret_cast<const uint2*>(hf) + (size_t)HOFF_U * 16;
    const uint2* hB = reinterpret_cast<const uint2*>(hf) + (size_t)HOFF_B * 16;
    const uint2* hI = reinterpret_cast<const uint2*>(hf) + (size_t)HOFF_I * 16;
    if (r < OFF_UI)      { ha = hU; hb = hB; na = NU; off = OFF_UB; rep = repUB; }
    else if (r < OFF_BI) { ha = hU; hb = hI; na = NU; off = OFF_UI; rep = repUI; }
    else                 { ha = hB; hb = hI; na = NB; off = OFF_BI; rep = repBI; }

    const uint2* ga; const uint2* gb; int gna;
    if (FIN) {
        ga = reinterpret_cast<const uint2*>(y1) + (size_t)off * 16;
        gb = ga;
        gna = N_TOT;
    } else {
        ga = ha; gb = hb; gna = na;
    }

    int beg = __ldg(rowptr + r), end = __ldg(rowptr + r + 1);
    float4 acc = make_float4(0.f, 0.f, 0.f, 0.f);

    uint2 x0q, y1q;
    int rl = r - off;
    if (FIN) {
        const uint2* x0r = (rl < na) ? ha + (size_t)rl * 16
                                     : hb + (size_t)(rl - na) * 16;
        x0q = __ldg(x0r + sub);
        y1q = __ldg(reinterpret_cast<const uint2*>(y1) + (size_t)r * 16 + sub);
    }

    for (int e0 = beg; e0 < end; e0 += 16) {
        int idx = e0 + sub;
        int c = 0; float v = 0.f;
        if (idx < end) {
            int2 p = __ldg(ccv + idx);
            c = p.x; v = __int_as_float(p.y);
        }
        int cnt = end - e0; if (cnt > 16) cnt = 16;
        int j = 0;
        for (; j + 2 <= cnt; j += 2) {
            int cj0 = __shfl_sync(mask, c, j, 16);
            float vj0 = __shfl_sync(mask, v, j, 16);
            int cj1 = __shfl_sync(mask, c, j + 1, 16);
            float vj1 = __shfl_sync(mask, v, j + 1, 16);
            const uint2* xr0 = (cj0 < gna) ? ga + (size_t)cj0 * 16
                                           : gb + (size_t)(cj0 - gna) * 16;
            const uint2* xr1 = (cj1 < gna) ? ga + (size_t)cj1 * 16
                                           : gb + (size_t)(cj1 - gna) * 16;
            uint2 q0 = __ldg(xr0 + sub);
            uint2 q1 = __ldg(xr1 + sub);
            float2 a0 = __half22float2(*reinterpret_cast<__half2*>(&q0.x));
            float2 a1 = __half22float2(*reinterpret_cast<__half2*>(&q0.y));
            float2 b0 = __half22float2(*reinterpret_cast<__half2*>(&q1.x));
            float2 b1 = __half22float2(*reinterpret_cast<__half2*>(&q1.y));
            acc.x = fmaf(vj0, a0.x, acc.x);
            acc.y = fmaf(vj0, a0.y, acc.y);
            acc.z = fmaf(vj0, a1.x, acc.z);
            acc.w = fmaf(vj0, a1.y, acc.w);
            acc.x = fmaf(vj1, b0.x, acc.x);
            acc.y = fmaf(vj1, b0.y, acc.y);
            acc.z = fmaf(vj1, b1.x, acc.z);
            acc.w = fmaf(vj1, b1.y, acc.w);
        }
        if (j < cnt) {
            int cj = __shfl_sync(mask, c, j, 16);
            float vj = __shfl_sync(mask, v, j, 16);
            const uint2* xr = (cj < gna) ? ga + (size_t)cj * 16
                                         : gb + (size_t)(cj - gna) * 16;
            uint2 q = __ldg(xr + sub);
            float2 f0 = __half22float2(*reinterpret_cast<__half2*>(&q.x));
            float2 f1 = __half22float2(*reinterpret_cast<__half2*>(&q.y));
            acc.x = fmaf(vj, f0.x, acc.x);
            acc.y = fmaf(vj, f0.y, acc.y);
            acc.z = fmaf(vj, f1.x, acc.z);
            acc.w = fmaf(vj, f1.y, acc.w);
        }
    }

    if (FIN) {
        float2 x0f0 = __half22float2(*reinterpret_cast<__half2*>(&x0q.x));
        float2 x0f1 = __half22float2(*reinterpret_cast<__half2*>(&x0q.y));
        float2 y1f0 = __half22float2(*reinterpret_cast<__half2*>(&y1q.x));
        float2 y1f1 = __half22float2(*reinterpret_cast<__half2*>(&y1q.y));
        const float s = 1.0f / 3.0f;
        __half2 h0 = __floats2half2_rn((acc.x + x0f0.x + y1f0.x) * s,
                                       (acc.y + x0f0.y + y1f0.y) * s);
        __half2 h1 = __floats2half2_rn((acc.z + x0f1.x + y1f1.x) * s,
                                       (acc.w + x0f1.y + y1f1.y) * s);
        uint2 o;
        o.x = *reinterpret_cast<unsigned*>(&h0);
        o.y = *reinterpret_cast<unsigned*>(&h1);
        reinterpret_cast<uint2*>(rep)[(size_t)rl * 16 + sub] = o;
    } else {
        __half2 h0 = __floats2half2_rn(acc.x, acc.y);
        __half2 h1 = __floats2half2_rn(acc.z, acc.w);
        uint2 o;
        o.x = *reinterpret_cast<unsigned*>(&h0);
        o.y = *reinterpret_cast<unsigned*>(&h1);
        reinterpret_cast<uint2*>(y1)[(size_t)r * 16 + sub] = o;
    }
}

// ---------------- scoring: fused tile-load + dot phase, 16 blocks/SM ----------------

__global__ void __launch_bounds__(128, 16)
score_kernel(const int* __restrict__ users, const int* __restrict__ bundles,
             const int* __restrict__ bundle_items,
             const __half* __restrict__ repUB,
             const __half* __restrict__ repUI,
             const __half* __restrict__ repBI,
             const float* __restrict__ cw1, const float* __restrict__ cb1,
             const float* __restrict__ cw2, const float* __restrict__ cb2,
             const float* __restrict__ sw1, const float* __restrict__ sb1,
             const float* __restrict__ sw2, const float* __restrict__ sb2,
             float* __restrict__ scores) {
    __shared__ float s_u[D];
    __shared__ float s_ubu[D];
    __shared__ float s_ubb[D];
    __shared__ float s_bbi[D];
    __shared__ int   s_idx[MAXDEG];
    __shared__ unsigned s_it2[MAXDEG * 33];   // items_ui half2 bits
    __shared__ float s_rUI[MAXDEG];
    __shared__ float s_rBI[MAXDEG];
    __shared__ float s_lg[MAXDEG];
    __shared__ float s_cw1[64];
    __shared__ float s_cb1[32];
    __shared__ float s_cw2[32];
    __shared__ float s_cb2v;
    __shared__ float s_cnt;
    __shared__ int   s_topi[CORE_K];
    __shared__ float s_topp[CORE_K];
    __shared__ unsigned char s_fringe[MAXDEG];
    __shared__ float s_core[D], s_fr[D], s_h1[D], s_hat[D];
    __shared__ float s_red[4];

    const int pair = blockIdx.x;
    const int b = pair / NCAND;
    const int tid = threadIdx.x;
    const int user = users[b];
    const int bun  = bundles[pair];

    const __half* UI_u = repUI;
    const __half* UB_u = repUB;
    const __half* UB_b = repUB + (size_t)NU * D;
    const __half* BI_b = repBI;
    const unsigned* UI_i_u = reinterpret_cast<const unsigned*>(repUI + (size_t)NU * D);
    const unsigned* BI_i_u = reinterpret_cast<const unsigned*>(repBI + (size_t)NB * D);

    if (tid < D) {
        s_u[tid]   = __half2float(UI_u[(size_t)user * D + tid]);
        s_ubu[tid] = __half2float(UB_u[(size_t)user * D + tid]);
        s_ubb[tid] = __half2float(UB_b[(size_t)bun * D + tid]);
        s_bbi[tid] = __half2float(BI_b[(size_t)bun * D + tid]);
        s_cw1[tid] = cw1[tid];
    }
    if (tid < MAXDEG) s_idx[tid] = bundle_items[(size_t)bun * MAXDEG + tid];
    if (tid < 32) { s_cb1[tid] = cb1[tid]; s_cw2[tid] = cw2[tid]; }
    if (tid == 0) s_cb2v = cb2[0];
    __syncthreads();

    // fused tile-load + dot phase: each warp handles one item m per iteration
    // (lanes = 32 half2 words). UI word cached to smem; both dots reduced inline.
    for (int i = tid; i < MAXDEG * 32; i += 128) {
        int m = i >> 5, d = i & 31;
        int ci = s_idx[m];
        bool ok = (ci < NI);
        unsigned q  = ok ? __ldg(UI_i_u + (size_t)ci * 32 + d) : 0u;
        unsigned qb = ok ? __ldg(BI_i_u + (size_t)ci * 32 + d) : 0u;
        s_it2[m * 33 + d] = q;
        float2 f = __half22float2(*reinterpret_cast<__half2*>(&q));
        float2 g = __half22float2(*reinterpret_cast<__half2*>(&qb));
        float a  = f.x * s_u[2 * d]   + f.y * s_u[2 * d + 1];
        float bs = g.x * s_bbi[2 * d] + g.y * s_bbi[2 * d + 1];
        #pragma unroll
        for (int o = 16; o; o >>= 1) {
            a  += __shfl_down_sync(0xffffffffu, a, o);
            bs += __shfl_down_sync(0xffffffffu, bs, o);
        }
        if (d == 0) { s_rUI[m] = a; s_rBI[m] = bs; }
    }
    __syncthreads();

    // core MLP -> masked logits
    if (tid < MAXDEG) {
        float logit;
        if (s_idx[tid] < NI) {
            float ru = s_rUI[tid], rb = s_rBI[tid];
            float acc = s_cb2v;
            #pragma unroll
            for (int j = 0; j < 32; j++) {
                float h = fmaf(ru, s_cw1[j], fmaf(rb, s_cw1[32 + j], s_cb1[j]));
                h = fmaxf(h, 0.f);
                acc = fmaf(h, s_cw2[j], acc);
            }
            logit = acc;
        } else {
            logit = -INFINITY;
        }
        s_lg[tid] = logit;
    }
    __syncthreads();

    // warp 0: max + top-3 via parallel argmax
    if (tid < 32) {
        float l1 = (tid < MAXDEG) ? s_lg[tid] : -INFINITY;
        float l2 = (tid + 32 < MAXDEG) ? s_lg[tid + 32] : -INFINITY;
        float mx = fmaxf(l1, l2);
        #pragma unroll
        for (int o = 16; o; o >>= 1) mx = fmaxf(mx, __shfl_xor_sync(0xffffffffu, mx, o));
        bool t1 = false, t2 = false;
        float e0v = 0.f, e1v = 0.f, e2v = 0.f;
        #pragma unroll
        for (int k = 0; k < CORE_K; k++) {
            float bv = t1 ? -INFINITY : l1;
            int bi_ = tid;
            if (!t2 && l2 > bv) { bv = l2; bi_ = tid + 32; }
            #pragma unroll
            for (int o = 16; o; o >>= 1) {
                float ov = __shfl_down_sync(0xffffffffu, bv, o);
                int oi = __shfl_down_sync(0xffffffffu, bi_, o);
                if (ov > bv || (ov == bv && oi < bi_)) { bv = ov; bi_ = oi; }
            }
            bv = __shfl_sync(0xffffffffu, bv, 0);
            bi_ = __shfl_sync(0xffffffffu, bi_, 0);
            if (bi_ == tid) t1 = true;
            if (bi_ == tid + 32) t2 = true;
            float ev = expf(bv - mx);
            if (k == 0) e0v = ev;
            else if (k == 1) e1v = ev;
            else e2v = ev;
            if (tid == 0) s_topi[k] = bi_;
        }
        if (tid == 0) {
            float es = e0v + e1v + e2v;
            float inv = 1.0f / es;
            s_topp[0] = e0v * inv;
            s_topp[1] = e1v * inv;
            s_topp[2] = e2v * inv;
        }
    }
    __syncthreads();

    if (tid < MAXDEG) {
        bool ok = (s_idx[tid] < NI) && tid != s_topi[0] && tid != s_topi[1]
                  && tid != s_topi[2];
        s_fringe[tid] = ok ? 1 : 0;
    }
    __syncthreads();
    if (tid < 32) {
        bool f1 = s_fringe[tid] != 0;
        bool f2 = (tid + 32 < MAXDEG) ? (s_fringe[tid + 32] != 0) : false;
        unsigned m1 = __ballot_sync(0xffffffffu, f1);
        unsigned m2 = __ballot_sync(0xffffffffu, f2);
        if (tid == 0) {
            int cnt = __popc(m1) + __popc(m2);
            s_cnt = fmaxf((float)cnt, 1.0f);
        }
    }
    __syncthreads();

    if (tid < D) {
        int hw = tid >> 1;
        int sel = tid & 1;
        float hc = 0.f;
        #pragma unroll
        for (int k = 0; k < CORE_K; k++) {
            unsigned q = s_it2[s_topi[k] * 33 + hw];
            float2 f = __half22float2(*reinterpret_cast<__half2*>(&q));
            hc = fmaf(sel ? f.y : f.x, s_topp[k], hc);
        }
        float fs = 0.f;
        for (int m = 0; m < MAXDEG; m++) {
            if (s_fringe[m]) {
                unsigned q = s_it2[m * 33 + hw];
                float2 f = __half22float2(*reinterpret_cast<__half2*>(&q));
                fs += sel ? f.y : f.x;
            }
        }
        s_core[tid] = hc;
        s_fr[tid] = fs / s_cnt;
    }
    __syncthreads();

    if (tid < D) {
        float acc = sb1[tid];
        #pragma unroll 8
        for (int i = 0; i < D; i++) acc = fmaf(s_core[i], sw1[i * D + tid], acc);
        #pragma unroll 8
        for (int i = 0; i < D; i++) acc = fmaf(s_fr[i], sw1[(D + i) * D + tid], acc);
        s_h1[tid] = fmaxf(acc, 0.f);
    }
    __syncthreads();
    if (tid < D) {
        float acc = sb2[tid];
        #pragma unroll 8
        for (int j = 0; j < D; j++) acc = fmaf(s_h1[j], sw2[j * D + tid], acc);
        s_hat[tid] = s_core[tid] + acc;
    }
    __syncthreads();

    const int w = tid >> 5, l = tid & 31;
    float part = 0.f;
    if (tid < D) part = s_u[tid] * s_ubb[tid] + s_ubu[tid] * s_hat[tid];
    #pragma unroll
    for (int o = 16; o; o >>= 1) part += __shfl_down_sync(0xffffffffu, part, o);
    if (l == 0) s_red[w] = part;
    __syncthreads();
    if (tid == 0) scores[pair] = s_red[0] + s_red[1] + s_red[2] + s_red[3];
}

__global__ void loss_kernel(const float* __restrict__ scores, float* __restrict__ out) {
    __shared__ float red[8];
    float acc = 0.f;
    for (int b = threadIdx.x; b < BATCH; b += blockDim.x) {
        float x = scores[b * 2 + 1] - scores[b * 2 + 0];
        float sp = (x > 0.f) ? x + log1pf(expf(-x)) : log1pf(expf(x));
        acc += sp;
    }
    #pragma unroll
    for (int o = 16; o; o >>= 1) acc += __shfl_down_sync(0xffffffffu, acc, o);
    if ((threadIdx.x & 31) == 0) red[threadIdx.x >> 5] = acc;
    __syncthreads();
    if (threadIdx.x == 0) {
        float s = 0.f;
        for (int i = 0; i < 8; i++) s += red[i];
        out[0] = s * (1.0f / BATCH);
    }
}

// ---------------- host ----------------

extern "C" void kernel_launch(void* const* d_in, const int* in_sizes, int n_in,
                              void* d_out, int out_size) {
    const float* uf  = (const float*)d_in[0];
    const float* bf  = (const float*)d_in[1];
    const float* itf = (const float*)d_in[2];
    const float* cw1 = (const float*)d_in[3];
    const float* cb1 = (const float*)d_in[4];
    const float* cw2 = (const float*)d_in[5];
    const float* cb2 = (const float*)d_in[6];
    const float* sw1 = (const float*)d_in[7];
    const float* sb1 = (const float*)d_in[8];
    const float* sw2 = (const float*)d_in[9];
    const float* sb2 = (const float*)d_in[10];
    const float* ub_val = (const float*)d_in[11];
    const float* ui_val = (const float*)d_in[12];
    const float* bi_val = (const float*)d_in[13];
    const int* users   = (const int*)d_in[14];
    const int* bundles = (const int*)d_in[15];
    const int* ub_row = (const int*)d_in[16];
    const int* ub_col = (const int*)d_in[17];
    const int* ui_row = (const int*)d_in[18];
    const int* ui_col = (const int*)d_in[19];
    const int* bi_row = (const int*)d_in[20];
    const int* bi_col = (const int*)d_in[21];
    const int* bundle_items = (const int*)d_in[22];

    int Eub = in_sizes[11];
    int Eui = in_sizes[12];
    int Ebi = in_sizes[13];
    int Etot = Eub + Eui + Ebi;

    __half *hf, *y1, *repUB, *repUI, *repBI;
    float *scores;
    int *cnt, *rowptr, *part;
    int2 *ccv;
    cudaGetSymbolAddress((void**)&hf, g_hf);
    cudaGetSymbolAddress((void**)&y1, g_y1);
    cudaGetSymbolAddress((void**)&repUB, g_repUB);
    cudaGetSymbolAddress((void**)&repUI, g_repUI);
    cudaGetSymbolAddress((void**)&repBI, g_repBI);
    cudaGetSymbolAddress((void**)&scores, g_scores);
    cudaGetSymbolAddress((void**)&cnt, g_cnt);
    cudaGetSymbolAddress((void**)&rowptr, g_rowptr);
    cudaGetSymbolAddress((void**)&part, g_part);
    cudaGetSymbolAddress((void**)&ccv, g_ccv);

    int gE = (Etot + 255) / 256;
    int gN = (N_TOT + 255) / 256;
    int nblk = (N_TOT + SCAN_TILE - 1) / SCAN_TILE;
    int nF4 = NFEAT * 16;

    f2h_kernel<<<(nF4 + 255) / 256, 256>>>((const float4*)uf, (const float4*)bf,
                                           (const float4*)itf, (uint2*)hf, cnt);
    hist_all_kernel<<<gE, 256>>>(ub_row, ui_row, bi_row, Eub, Eui, Ebi, cnt);
    scan1_kernel<<<nblk, 256>>>(cnt, part, N_TOT);
    scan3_kernel<<<gN, 256>>>(cnt, part, rowptr, N_TOT, nblk, Etot);
    scatter_all_kernel<<<gE, 256>>>(ub_row, ub_col, ub_val,
                                    ui_row, ui_col, ui_val,
                                    bi_row, bi_col, bi_val,
                                    Eub, Eui, Ebi, cnt, ccv);

    int gS = (N_TOT * 16 + 255) / 256;
    spmm_all_kernel<false><<<gS, 256>>>(rowptr, ccv, hf, y1, repUB, repUI, repBI);
    spmm_all_kernel<true><<<gS, 256>>>(rowptr, ccv, hf, y1, repUB, repUI, repBI);

    score_kernel<<<BATCH * NCAND, 128>>>(users, bundles, bundle_items,
                                         repUB, repUI, repBI,
                                         cw1, cb1, cw2, cb2,
                                         sw1, sb1, sw2, sb2, scores);
    loss_kernel<<<1, 256>>>(scores, (float*)d_out);
}

// round 17
// speedup vs baseline: 1.3253x; 1.3253x over previous
#include <cuda_runtime.h>
#include <cuda_fp16.h>
#include <math.h>

#define D        64
#define NU       50000
#define NB       20000
#define NI       100000
#define N_UB     (NU + NB)
#define N_UI     (NU + NI)
#define N_BI     (NB + NI)
#define N_TOT    (N_UB + N_UI + N_BI)       /* 340000 */
#define OFF_UB   0
#define OFF_UI   N_UB                        /* 70000 */
#define OFF_BI   (N_UB + N_UI)               /* 220000 */
#define NFEAT    (NU + NB + NI)              /* 170000 */
#define HOFF_U   0
#define HOFF_B   NU
#define HOFF_I   (NU + NB)
#define MAXDEG   50
#define BATCH    2048
#define NCAND    2
#define CORE_K   3
#define EMAXTOT  3000000
#define SCAN_TILE 2048

// ---------------- scratch (allocation-free rule: device globals) ----------------
__device__ __half g_hf[(size_t)NFEAT * D];     // fp16 base features (U, B, I)
__device__ __half g_y1[(size_t)N_TOT * D];     // fp16 layer-1 output
__device__ __half g_repUB[(size_t)N_UB * D];   // final reps (fp16)
__device__ __half g_repUI[(size_t)N_UI * D];
__device__ __half g_repBI[(size_t)N_BI * D];
__device__ int    g_cnt[N_TOT];                // counts -> cursor
__device__ int    g_rowptr[N_TOT + 1];
__device__ int    g_part[256];
__device__ int2   g_ccv[EMAXTOT];              // packed (col, val bits)
__device__ float  g_scores[BATCH * NCAND];

// ---------------- f2h + zero cnt ----------------
__global__ void f2h_kernel(const float4* __restrict__ uf, const float4* __restrict__ bf,
                           const float4* __restrict__ itf, uint2* __restrict__ dst,
                           int* __restrict__ cnt) {
    int i = blockIdx.x * blockDim.x + threadIdx.x;
    if (i < N_TOT) cnt[i] = 0;
    const int nU = NU * 16, nB = NB * 16, nI = NI * 16;
    float4 v;
    if (i < nU) v = __ldg(uf + i);
    else if (i < nU + nB) v = __ldg(bf + (i - nU));
    else if (i < nU + nB + nI) v = __ldg(itf + (i - nU - nB));
    else return;
    __half2 h0 = __floats2half2_rn(v.x, v.y);
    __half2 h1 = __floats2half2_rn(v.z, v.w);
    uint2 o;
    o.x = *reinterpret_cast<unsigned*>(&h0);
    o.y = *reinterpret_cast<unsigned*>(&h1);
    dst[i] = o;
}

// ---------------- CSR build (batched over all 3 graphs) ----------------

__global__ void hist_all_kernel(const int* __restrict__ ubr, const int* __restrict__ uir,
                                const int* __restrict__ bir,
                                int Eub, int Eui, int Ebi,
                                int* __restrict__ cnt) {
    int e = blockIdx.x * blockDim.x + threadIdx.x;
    int r;
    if (e < Eub) r = __ldg(ubr + e) + OFF_UB;
    else if (e < Eub + Eui) r = __ldg(uir + (e - Eub)) + OFF_UI;
    else if (e < Eub + Eui + Ebi) r = __ldg(bir + (e - Eub - Eui)) + OFF_BI;
    else return;
    atomicAdd(&cnt[r], 1);
}

__global__ void scan1_kernel(int* __restrict__ data, int* __restrict__ part, int n) {
    __shared__ int sh[256];
    int tid = threadIdx.x;
    int base = blockIdx.x * SCAN_TILE + tid * 8;
    int v[8];
    int s = 0;
    #pragma unroll
    for (int k = 0; k < 8; k++) {
        v[k] = (base + k < n) ? data[base + k] : 0;
        s += v[k];
    }
    sh[tid] = s;
    __syncthreads();
    #pragma unroll
    for (int off = 1; off < 256; off <<= 1) {
        int t = (tid >= off) ? sh[tid - off] : 0;
        __syncthreads();
        sh[tid] += t;
        __syncthreads();
    }
    if (tid == 255) part[blockIdx.x] = sh[255];
    int run = sh[tid] - s;
    #pragma unroll
    for (int k = 0; k < 8; k++) {
        if (base + k < n) data[base + k] = run;
        run += v[k];
    }
}

__global__ void scan3_kernel(int* __restrict__ data, const int* __restrict__ part,
                             int* __restrict__ rowptr, int n, int np, int E) {
    __shared__ int sh[256];
    int tid = threadIdx.x;
    int s = (tid < np) ? part[tid] : 0;
    sh[tid] = s;
    __syncthreads();
    #pragma unroll
    for (int off = 1; off < 256; off <<= 1) {
        int t = (tid >= off) ? sh[tid - off] : 0;
        __syncthreads();
        sh[tid] += t;
        __syncthreads();
    }
    __syncthreads();
    int i = blockIdx.x * blockDim.x + tid;
    if (i < n) {
        int blk = i / SCAN_TILE;
        int v = data[i] + sh[blk] - ((blk < np) ? part[blk] : 0);
        rowptr[i] = v;
        data[i] = v;
    }
    if (i == 0) rowptr[n] = E;
}

__global__ void scatter_all_kernel(const int* __restrict__ ubr, const int* __restrict__ ubc,
                                   const float* __restrict__ ubv,
                                   const int* __restrict__ uir, const int* __restrict__ uic,
                                   const float* __restrict__ uiv,
                                   const int* __restrict__ bir, const int* __restrict__ bic,
                                   const float* __restrict__ biv,
                                   int Eub, int Eui, int Ebi,
                                   int* __restrict__ cursor,
                                   int2* __restrict__ ccv) {
    int e = blockIdx.x * blockDim.x + threadIdx.x;
    int r, c; float v;
    if (e < Eub) { r = __ldg(ubr + e) + OFF_UB; c = __ldg(ubc + e); v = __ldg(ubv + e); }
    else if (e < Eub + Eui) { int t = e - Eub; r = __ldg(uir + t) + OFF_UI; c = __ldg(uic + t); v = __ldg(uiv + t); }
    else if (e < Eub + Eui + Ebi) { int t = e - Eub - Eui; r = __ldg(bir + t) + OFF_BI; c = __ldg(bic + t); v = __ldg(biv + t); }
    else return;
    int p = atomicAdd(&cursor[r], 1);
    ccv[p] = make_int2(c, __float_as_int(v));
}

// ---------------- fused gather spmm, fp16 rows, 16 lanes/row, 2-deep ----------------
template <bool FIN>
__global__ void __launch_bounds__(256)
spmm_all_kernel(const int* __restrict__ rowptr, const int2* __restrict__ ccv,
                const __half* __restrict__ hf, __half* __restrict__ y1,
                __half* __restrict__ repUB, __half* __restrict__ repUI,
                __half* __restrict__ repBI) {
    int g = blockIdx.x * blockDim.x + threadIdx.x;
    int r = g >> 4;
    if (r >= N_TOT) return;
    int lane = threadIdx.x & 31;
    int sub = lane & 15;
    unsigned mask = (lane < 16) ? 0x0000FFFFu : 0xFFFF0000u;

    const uint2* ha; const uint2* hb; int na; int off; __half* rep;
    const uint2* hU = reinterpret_cast<const uint2*>(hf) + (size_t)HOFF_U * 16;
    const uint2* hB = reinterpret_cast<const uint2*>(hf) + (size_t)HOFF_B * 16;
    const uint2* hI = reinterpret_cast<const uint2*>(hf) + (size_t)HOFF_I * 16;
    if (r < OFF_UI)      { ha = hU; hb = hB; na = NU; off = OFF_UB; rep = repUB; }
    else if (r < OFF_BI) { ha = hU; hb = hI; na = NU; off = OFF_UI; rep = repUI; }
    else                 { ha = hB; hb = hI; na = NB; off = OFF_BI; rep = repBI; }

    const uint2* ga; const uint2* gb; int gna;
    if (FIN) {
        ga = reinterpret_cast<const uint2*>(y1) + (size_t)off * 16;
        gb = ga;
        gna = N_TOT;
    } else {
        ga = ha; gb = hb; gna = na;
    }

    int beg = __ldg(rowptr + r), end = __ldg(rowptr + r + 1);
    float4 acc = make_float4(0.f, 0.f, 0.f, 0.f);

    uint2 x0q, y1q;
    int rl = r - off;
    if (FIN) {
        const uint2* x0r = (rl < na) ? ha + (size_t)rl * 16
                                     : hb + (size_t)(rl - na) * 16;
        x0q = __ldg(x0r + sub);
        y1q = __ldg(reinterpret_cast<const uint2*>(y1) + (size_t)r * 16 + sub);
    }

    for (int e0 = beg; e0 < end; e0 += 16) {
        int idx = e0 + sub;
        int c = 0; float v = 0.f;
        if (idx < end) {
            int2 p = __ldg(ccv + idx);
            c = p.x; v = __int_as_float(p.y);
        }
        int cnt = end - e0; if (cnt > 16) cnt = 16;
        int j = 0;
        for (; j + 2 <= cnt; j += 2) {
            int cj0 = __shfl_sync(mask, c, j, 16);
            float vj0 = __shfl_sync(mask, v, j, 16);
            int cj1 = __shfl_sync(mask, c, j + 1, 16);
            float vj1 = __shfl_sync(mask, v, j + 1, 16);
            const uint2* xr0 = (cj0 < gna) ? ga + (size_t)cj0 * 16
                                           : gb + (size_t)(cj0 - gna) * 16;
            const uint2* xr1 = (cj1 < gna) ? ga + (size_t)cj1 * 16
                                           : gb + (size_t)(cj1 - gna) * 16;
            uint2 q0 = __ldg(xr0 + sub);
            uint2 q1 = __ldg(xr1 + sub);
            float2 a0 = __half22float2(*reinterpret_cast<__half2*>(&q0.x));
            float2 a1 = __half22float2(*reinterpret_cast<__half2*>(&q0.y));
            float2 b0 = __half22float2(*reinterpret_cast<__half2*>(&q1.x));
            float2 b1 = __half22float2(*reinterpret_cast<__half2*>(&q1.y));
            acc.x = fmaf(vj0, a0.x, acc.x);
            acc.y = fmaf(vj0, a0.y, acc.y);
            acc.z = fmaf(vj0, a1.x, acc.z);
            acc.w = fmaf(vj0, a1.y, acc.w);
            acc.x = fmaf(vj1, b0.x, acc.x);
            acc.y = fmaf(vj1, b0.y, acc.y);
            acc.z = fmaf(vj1, b1.x, acc.z);
            acc.w = fmaf(vj1, b1.y, acc.w);
        }
        if (j < cnt) {
            int cj = __shfl_sync(mask, c, j, 16);
            float vj = __shfl_sync(mask, v, j, 16);
            const uint2* xr = (cj < gna) ? ga + (size_t)cj * 16
                                         : gb + (size_t)(cj - gna) * 16;
            uint2 q = __ldg(xr + sub);
            float2 f0 = __half22float2(*reinterpret_cast<__half2*>(&q.x));
            float2 f1 = __half22float2(*reinterpret_cast<__half2*>(&q.y));
            acc.x = fmaf(vj, f0.x, acc.x);
            acc.y = fmaf(vj, f0.y, acc.y);
            acc.z = fmaf(vj, f1.x, acc.z);
            acc.w = fmaf(vj, f1.y, acc.w);
        }
    }

    if (FIN) {
        float2 x0f0 = __half22float2(*reinterpret_cast<__half2*>(&x0q.x));
        float2 x0f1 = __half22float2(*reinterpret_cast<__half2*>(&x0q.y));
        float2 y1f0 = __half22float2(*reinterpret_cast<__half2*>(&y1q.x));
        float2 y1f1 = __half22float2(*reinterpret_cast<__half2*>(&y1q.y));
        const float s = 1.0f / 3.0f;
        __half2 h0 = __floats2half2_rn((acc.x + x0f0.x + y1f0.x) * s,
                                       (acc.y + x0f0.y + y1f0.y) * s);
        __half2 h1 = __floats2half2_rn((acc.z + x0f1.x + y1f1.x) * s,
                                       (acc.w + x0f1.y + y1f1.y) * s);
        uint2 o;
        o.x = *reinterpret_cast<unsigned*>(&h0);
        o.y = *reinterpret_cast<unsigned*>(&h1);
        reinterpret_cast<uint2*>(rep)[(size_t)rl * 16 + sub] = o;
    } else {
        __half2 h0 = __floats2half2_rn(acc.x, acc.y);
        __half2 h1 = __floats2half2_rn(acc.z, acc.w);
        uint2 o;
        o.x = *reinterpret_cast<unsigned*>(&h0);
        o.y = *reinterpret_cast<unsigned*>(&h1);
        reinterpret_cast<uint2*>(y1)[(size_t)r * 16 + sub] = o;
    }
}

// ---------------- scoring: fp16 reps, half2 smem tile, 16 blocks/SM ----------------

__global__ void __launch_bounds__(128, 16)
score_kernel(const int* __restrict__ users, const int* __restrict__ bundles,
             const int* __restrict__ bundle_items,
             const __half* __restrict__ repUB,
             const __half* __restrict__ repUI,
             const __half* __restrict__ repBI,
             const float* __restrict__ cw1, const float* __restrict__ cb1,
             const float* __restrict__ cw2, const float* __restrict__ cb2,
             const float* __restrict__ sw1, const float* __restrict__ sb1,
             const float* __restrict__ sw2, const float* __restrict__ sb2,
             float* __restrict__ scores) {
    __shared__ float s_u[D];
    __shared__ float s_ubu[D];
    __shared__ float s_ubb[D];
    __shared__ float s_bbi[D];
    __shared__ int   s_idx[MAXDEG];
    __shared__ unsigned s_it2[MAXDEG * 33];
    __shared__ float s_rUI[MAXDEG];
    __shared__ float s_rBI[MAXDEG];
    __shared__ float s_lg[MAXDEG];
    __shared__ float s_cw1[64];
    __shared__ float s_cb1[32];
    __shared__ float s_cw2[32];
    __shared__ float s_cb2v;
    __shared__ float s_cnt;
    __shared__ int   s_topi[CORE_K];
    __shared__ float s_topp[CORE_K];
    __shared__ unsigned char s_fringe[MAXDEG];
    __shared__ float s_core[D], s_fr[D], s_h1[D], s_hat[D];
    __shared__ float s_red[4];

    const int pair = blockIdx.x;
    const int b = pair / NCAND;
    const int tid = threadIdx.x;
    const int user = users[b];
    const int bun  = bundles[pair];

    const __half* UI_u = repUI;
    const __half* UB_u = repUB;
    const __half* UB_b = repUB + (size_t)NU * D;
    const __half* BI_b = repBI;
    const unsigned* UI_i_u = reinterpret_cast<const unsigned*>(repUI + (size_t)NU * D);
    const unsigned* BI_i_u = reinterpret_cast<const unsigned*>(repBI + (size_t)NB * D);

    if (tid < D) {
        s_u[tid]   = __half2float(UI_u[(size_t)user * D + tid]);
        s_ubu[tid] = __half2float(UB_u[(size_t)user * D + tid]);
        s_ubb[tid] = __half2float(UB_b[(size_t)bun * D + tid]);
        s_bbi[tid] = __half2float(BI_b[(size_t)bun * D + tid]);
        s_cw1[tid] = cw1[tid];
    }
    if (tid < MAXDEG) s_idx[tid] = bundle_items[(size_t)bun * MAXDEG + tid];
    if (tid < 32) { s_cb1[tid] = cb1[tid]; s_cw2[tid] = cw2[tid]; }
    if (tid == 0) s_cb2v = cb2[0];
    __syncthreads();

    for (int i = tid; i < MAXDEG * 32; i += 128) {
        int m = i >> 5, d = i & 31;
        int ci = s_idx[m];
        s_it2[m * 33 + d] = (ci < NI) ? __ldg(UI_i_u + (size_t)ci * 32 + d) : 0u;
    }
    __syncthreads();

    // r_UI, r_BI: one warp per item; BI row load software-pipelined (next
    // iteration's load issued before this iteration's reductions)
    const int w = tid >> 5, l = tid & 31;
    {
        int ci0 = (w < MAXDEG) ? s_idx[w] : NI;
        unsigned qb_next = (ci0 < NI) ? __ldg(BI_i_u + (size_t)ci0 * 32 + l) : 0u;
        for (int m = w; m < MAXDEG; m += 4) {
            unsigned qb = qb_next;
            int mn = m + 4;
            int cin = (mn < MAXDEG) ? s_idx[mn] : NI;
            qb_next = (cin < NI) ? __ldg(BI_i_u + (size_t)cin * 32 + l) : 0u;

            unsigned q = s_it2[m * 33 + l];
            float2 f = __half22float2(*reinterpret_cast<__half2*>(&q));
            float2 g = __half22float2(*reinterpret_cast<__half2*>(&qb));
            float a  = f.x * s_u[2 * l]   + f.y * s_u[2 * l + 1];
            float bs = g.x * s_bbi[2 * l] + g.y * s_bbi[2 * l + 1];
            #pragma unroll
            for (int o = 16; o; o >>= 1) {
                a  += __shfl_down_sync(0xffffffffu, a, o);
                bs += __shfl_down_sync(0xffffffffu, bs, o);
            }
            if (l == 0) { s_rUI[m] = a; s_rBI[m] = bs; }
        }
    }
    __syncthreads();

    if (tid < MAXDEG) {
        float logit;
        if (s_idx[tid] < NI) {
            float ru = s_rUI[tid], rb = s_rBI[tid];
            float acc = s_cb2v;
            #pragma unroll
            for (int j = 0; j < 32; j++) {
                float h = fmaf(ru, s_cw1[j], fmaf(rb, s_cw1[32 + j], s_cb1[j]));
                h = fmaxf(h, 0.f);
                acc = fmaf(h, s_cw2[j], acc);
            }
            logit = acc;
        } else {
            logit = -INFINITY;
        }
        s_lg[tid] = logit;
    }
    __syncthreads();

    if (tid < 32) {
        float l1 = (tid < MAXDEG) ? s_lg[tid] : -INFINITY;
        float l2 = (tid + 32 < MAXDEG) ? s_lg[tid + 32] : -INFINITY;
        float mx = fmaxf(l1, l2);
        #pragma unroll
        for (int o = 16; o; o >>= 1) mx = fmaxf(mx, __shfl_xor_sync(0xffffffffu, mx, o));
        bool t1 = false, t2 = false;
        float e0v = 0.f, e1v = 0.f, e2v = 0.f;
        #pragma unroll
        for (int k = 0; k < CORE_K; k++) {
            float bv = t1 ? -INFINITY : l1;
            int bi_ = tid;
            if (!t2 && l2 > bv) { bv = l2; bi_ = tid + 32; }
            #pragma unroll
            for (int o = 16; o; o >>= 1) {
                float ov = __shfl_down_sync(0xffffffffu, bv, o);
                int oi = __shfl_down_sync(0xffffffffu, bi_, o);
                if (ov > bv || (ov == bv && oi < bi_)) { bv = ov; bi_ = oi; }
            }
            bv = __shfl_sync(0xffffffffu, bv, 0);
            bi_ = __shfl_sync(0xffffffffu, bi_, 0);
            if (bi_ == tid) t1 = true;
            if (bi_ == tid + 32) t2 = true;
            float ev = expf(bv - mx);
            if (k == 0) e0v = ev;
            else if (k == 1) e1v = ev;
            else e2v = ev;
            if (tid == 0) s_topi[k] = bi_;
        }
        if (tid == 0) {
            float es = e0v + e1v + e2v;
            float inv = 1.0f / es;
            s_topp[0] = e0v * inv;
            s_topp[1] = e1v * inv;
            s_topp[2] = e2v * inv;
        }
    }
    __syncthreads();

    if (tid < MAXDEG) {
        bool ok = (s_idx[tid] < NI) && tid != s_topi[0] && tid != s_topi[1]
                  && tid != s_topi[2];
        s_fringe[tid] = ok ? 1 : 0;
    }
    __syncthreads();
    if (tid < 32) {
        bool f1 = s_fringe[tid] != 0;
        bool f2 = (tid + 32 < MAXDEG) ? (s_fringe[tid + 32] != 0) : false;
        unsigned m1 = __ballot_sync(0xffffffffu, f1);
        unsigned m2 = __ballot_sync(0xffffffffu, f2);
        if (tid == 0) {
            int cnt = __popc(m1) + __popc(m2);
            s_cnt = fmaxf((float)cnt, 1.0f);
        }
    }
    __syncthreads();

    if (tid < D) {
        int hw = tid >> 1;
        int sel = tid & 1;
        float hc = 0.f;
        #pragma unroll
        for (int k = 0; k < CORE_K; k++) {
            unsigned q = s_it2[s_topi[k] * 33 + hw];
            float2 f = __half22float2(*reinterpret_cast<__half2*>(&q));
            hc = fmaf(sel ? f.y : f.x, s_topp[k], hc);
        }
        float fs = 0.f;
        for (int m = 0; m < MAXDEG; m++) {
            if (s_fringe[m]) {
                unsigned q = s_it2[m * 33 + hw];
                float2 f = __half22float2(*reinterpret_cast<__half2*>(&q));
                fs += sel ? f.y : f.x;
            }
        }
        s_core[tid] = hc;
        s_fr[tid] = fs / s_cnt;
    }
    __syncthreads();

    if (tid < D) {
        float acc = sb1[tid];
        #pragma unroll 8
        for (int i = 0; i < D; i++) acc = fmaf(s_core[i], sw1[i * D + tid], acc);
        #pragma unroll 8
        for (int i = 0; i < D; i++) acc = fmaf(s_fr[i], sw1[(D + i) * D + tid], acc);
        s_h1[tid] = fmaxf(acc, 0.f);
    }
    __syncthreads();
    if (tid < D) {
        float acc = sb2[tid];
        #pragma unroll 8
        for (int j = 0; j < D; j++) acc = fmaf(s_h1[j], sw2[j * D + tid], acc);
        s_hat[tid] = s_core[tid] + acc;
    }
    __syncthreads();

    float part = 0.f;
    if (tid < D) part = s_u[tid] * s_ubb[tid] + s_ubu[tid] * s_hat[tid];
    #pragma unroll
    for (int o = 16; o; o >>= 1) part += __shfl_down_sync(0xffffffffu, part, o);
    if (l == 0) s_red[w] = part;
    __syncthreads();
    if (tid == 0) scores[pair] = s_red[0] + s_red[1] + s_red[2] + s_red[3];
}

__global__ void loss_kernel(const float* __restrict__ scores, float* __restrict__ out) {
    __shared__ float red[8];
    float acc = 0.f;
    for (int b = threadIdx.x; b < BATCH; b += blockDim.x) {
        float x = scores[b * 2 + 1] - scores[b * 2 + 0];
        float sp = (x > 0.f) ? x + log1pf(expf(-x)) : log1pf(expf(x));
        acc += sp;
    }
    #pragma unroll
    for (int o = 16; o; o >>= 1) acc += __shfl_down_sync(0xffffffffu, acc, o);
    if ((threadIdx.x & 31) == 0) red[threadIdx.x >> 5] = acc;
    __syncthreads();
    if (threadIdx.x == 0) {
        float s = 0.f;
        for (int i = 0; i < 8; i++) s += red[i];
        out[0] = s * (1.0f / BATCH);
    }
}

// ---------------- host ----------------

extern "C" void kernel_launch(void* const* d_in, const int* in_sizes, int n_in,
                              void* d_out, int out_size) {
    const float* uf  = (const float*)d_in[0];
    const float* bf  = (const float*)d_in[1];
    const float* itf = (const float*)d_in[2];
    const float* cw1 = (const float*)d_in[3];
    const float* cb1 = (const float*)d_in[4];
    const float* cw2 = (const float*)d_in[5];
    const float* cb2 = (const float*)d_in[6];
    const float* sw1 = (const float*)d_in[7];
    const float* sb1 = (const float*)d_in[8];
    const float* sw2 = (const float*)d_in[9];
    const float* sb2 = (const float*)d_in[10];
    const float* ub_val = (const float*)d_in[11];
    const float* ui_val = (const float*)d_in[12];
    const float* bi_val = (const float*)d_in[13];
    const int* users   = (const int*)d_in[14];
    const int* bundles = (const int*)d_in[15];
    const int* ub_row = (const int*)d_in[16];
    const int* ub_col = (const int*)d_in[17];
    const int* ui_row = (const int*)d_in[18];
    const int* ui_col = (const int*)d_in[19];
    const int* bi_row = (const int*)d_in[20];
    const int* bi_col = (const int*)d_in[21];
    const int* bundle_items = (const int*)d_in[22];

    int Eub = in_sizes[11];
    int Eui = in_sizes[12];
    int Ebi = in_sizes[13];
    int Etot = Eub + Eui + Ebi;

    __half *hf, *y1, *repUB, *repUI, *repBI;
    float *scores;
    int *cnt, *rowptr, *part;
    int2 *ccv;
    cudaGetSymbolAddress((void**)&hf, g_hf);
    cudaGetSymbolAddress((void**)&y1, g_y1);
    cudaGetSymbolAddress((void**)&repUB, g_repUB);
    cudaGetSymbolAddress((void**)&repUI, g_repUI);
    cudaGetSymbolAddress((void**)&repBI, g_repBI);
    cudaGetSymbolAddress((void**)&scores, g_scores);
    cudaGetSymbolAddress((void**)&cnt, g_cnt);
    cudaGetSymbolAddress((void**)&rowptr, g_rowptr);
    cudaGetSymbolAddress((void**)&part, g_part);
    cudaGetSymbolAddress((void**)&ccv, g_ccv);

    int gE = (Etot + 255) / 256;
    int gN = (N_TOT + 255) / 256;
    int nblk = (N_TOT + SCAN_TILE - 1) / SCAN_TILE;
    int nF4 = NFEAT * 16;

    f2h_kernel<<<(nF4 + 255) / 256, 256>>>((const float4*)uf, (const float4*)bf,
                                           (const float4*)itf, (uint2*)hf, cnt);
    hist_all_kernel<<<gE, 256>>>(ub_row, ui_row, bi_row, Eub, Eui, Ebi, cnt);
    scan1_kernel<<<nblk, 256>>>(cnt, part, N_TOT);
    scan3_kernel<<<gN, 256>>>(cnt, part, rowptr, N_TOT, nblk, Etot);
    scatter_all_kernel<<<gE, 256>>>(ub_row, ub_col, ub_val,
                                    ui_row, ui_col, ui_val,
                                    bi_row, bi_col, bi_val,
                                    Eub, Eui, Ebi, cnt, ccv);

    int gS = (N_TOT * 16 + 255) / 256;
    spmm_all_kernel<false><<<gS, 256>>>(rowptr, ccv, hf, y1, repUB, repUI, repBI);
    spmm_all_kernel<true><<<gS, 256>>>(rowptr, ccv, hf, y1, repUB, repUI, repBI);

    score_kernel<<<BATCH * NCAND, 128>>>(users, bundles, bundle_items,
                                         repUB, repUI, repBI,
                                         cw1, cb1, cw2, cb2,
                                         sw1, sb1, sw2, sb2, scores);
    loss_kernel<<<1, 256>>>(scores, (float*)d_out);
}